// round 1
// baseline (speedup 1.0000x reference)
#include <cuda_runtime.h>
#include <math.h>
#include <stdint.h>

#define B_TOK 1024
#define NA    32
#define DZ    96
#define DA    32
#define DD    128
#define NE    8
#define FF    1024
#define HH    512
#define NR    4
#define QS    385   // padded qkv row stride (conflict-free lane-strided access)

// ---------------- device scratch (no allocations allowed) ----------------
__device__ float g_slot[2u * B_TOK * NA * DD];   // gate-scaled expert outputs, 32 MB
__device__ float g_t[B_TOK * HH];                // head hidden, 2 MB
__device__ int   g_sel_idx[B_TOK * 2];
__device__ float g_sel_gate[B_TOK * 2];
__device__ float g_lse_tok[B_TOK];

// ---------------- generic 32xN = 32xK @ KxN(T) microkernel ----------------
// As: [32][SA] in smem (row-major, lane-uniform reads -> broadcast LDS)
// W:  [N][K] row-major in gmem (L2-hot)
// Out: [32][SO] in smem.  MODE: 0 = +bias, 1 = +bias,relu, 2 = +bias,+Res
template<int K, int N, int SA, int SO, int MODE>
__device__ __forceinline__ void gemm32(const float* __restrict__ As,
                                       const float* __restrict__ W,
                                       const float* __restrict__ bias,
                                       float* __restrict__ Out,
                                       const float* __restrict__ Res,
                                       int wid, int lane)
{
    const int row0 = wid * 4;
    #pragma unroll 1
    for (int it = 0; it < N / 64; ++it) {
        const int j0 = it * 64 + lane * 2;
        float acc[4][2] = {};
        const float* w0p = W + (size_t)j0 * K;
        const float* w1p = w0p + K;
        #pragma unroll 4
        for (int k = 0; k < K; k += 4) {
            float4 w0 = *reinterpret_cast<const float4*>(w0p + k);
            float4 w1 = *reinterpret_cast<const float4*>(w1p + k);
            #pragma unroll
            for (int r = 0; r < 4; ++r) {
                float4 xa = *reinterpret_cast<const float4*>(As + (row0 + r) * SA + k);
                acc[r][0] += xa.x * w0.x + xa.y * w0.y + xa.z * w0.z + xa.w * w0.w;
                acc[r][1] += xa.x * w1.x + xa.y * w1.y + xa.z * w1.z + xa.w * w1.w;
            }
        }
        #pragma unroll
        for (int r = 0; r < 4; ++r) {
            #pragma unroll
            for (int c = 0; c < 2; ++c) {
                int i = row0 + r, j = j0 + c;
                float v = acc[r][c] + bias[j];
                if (MODE == 1) v = fmaxf(v, 0.0f);
                if (MODE == 2) v += Res[i * SO + j];
                Out[i * SO + j] = v;
            }
        }
    }
}

// in-place LayerNorm over last dim (128) for 32 rows; warp wid owns rows 4w..4w+3
__device__ __forceinline__ void ln_rows(float* __restrict__ buf,
                                        const float* __restrict__ g,
                                        const float* __restrict__ b,
                                        int wid, int lane)
{
    __syncwarp();
    #pragma unroll
    for (int r = 0; r < 4; ++r) {
        int i = wid * 4 + r;
        float v[4], s = 0.f, ss = 0.f;
        #pragma unroll
        for (int u = 0; u < 4; ++u) {
            v[u] = buf[i * DD + lane + 32 * u];
            s += v[u]; ss += v[u] * v[u];
        }
        #pragma unroll
        for (int off = 16; off; off >>= 1) {
            s  += __shfl_xor_sync(0xffffffffu, s,  off);
            ss += __shfl_xor_sync(0xffffffffu, ss, off);
        }
        float mu = s * (1.0f / DD);
        float var = ss * (1.0f / DD) - mu * mu;
        float rstd = rsqrtf(var + 1e-5f);
        #pragma unroll
        for (int u = 0; u < 4; ++u) {
            int c = lane + 32 * u;
            buf[i * DD + c] = (v[u] - mu) * rstd * g[c] + b[c];
        }
    }
}

// ---------------- router: logits, top-2 gates, per-token logsumexp ----------------
__global__ void router_kernel(const float* __restrict__ z, const float* __restrict__ a,
                              const float* __restrict__ w_gate, float* __restrict__ gates_out)
{
    const int b = blockIdx.x;
    const int tid = threadIdx.x;
    float acc[NE] = {};
    for (int k = tid; k < NA * DD; k += 128) {
        int i = k >> 7, c = k & 127;
        float xv = (c < DZ) ? z[(b * NA + i) * DZ + c] : a[(b * NA + i) * DA + (c - DZ)];
        const float* wr = w_gate + (size_t)k * NE;
        #pragma unroll
        for (int e = 0; e < NE; ++e) acc[e] += xv * wr[e];
    }
    __shared__ float red[128 * NE];
    __shared__ float logits[NE];
    #pragma unroll
    for (int e = 0; e < NE; ++e) red[tid * NE + e] = acc[e];
    __syncthreads();
    if (tid < NE) {
        float s = 0.f;
        for (int t = 0; t < 128; ++t) s += red[t * NE + tid];
        logits[tid] = s;
    }
    __syncthreads();
    if (tid == 0) {
        // top-2 (stable, matches lax.top_k ordering)
        int i0 = 0;
        #pragma unroll
        for (int e = 1; e < NE; ++e) if (logits[e] > logits[i0]) i0 = e;
        int i1 = (i0 == 0) ? 1 : 0;
        #pragma unroll
        for (int e = 0; e < NE; ++e) if (e != i0 && logits[e] > logits[i1]) i1 = e;
        float l0 = logits[i0], l1 = logits[i1];
        float m2 = fmaxf(l0, l1);
        float e0 = expf(l0 - m2), e1 = expf(l1 - m2);
        float inv = 1.0f / (e0 + e1);
        float g0 = e0 * inv, g1 = e1 * inv;
        #pragma unroll
        for (int e = 0; e < NE; ++e)
            gates_out[b * NE + e] = (e == i0) ? g0 : ((e == i1) ? g1 : 0.0f);
        g_sel_idx[b * 2 + 0] = i0;  g_sel_gate[b * 2 + 0] = g0;
        g_sel_idx[b * 2 + 1] = i1;  g_sel_gate[b * 2 + 1] = g1;
        float m = logits[0];
        #pragma unroll
        for (int e = 1; e < NE; ++e) m = fmaxf(m, logits[e]);
        float s = 0.f;
        #pragma unroll
        for (int e = 0; e < NE; ++e) s += expf(logits[e] - m);
        g_lse_tok[b] = m + logf(s);
    }
}

// ---------------- expert: (token, slot) per block ----------------
__global__ void __launch_bounds__(256, 1)
expert_kernel(const float* __restrict__ z, const float* __restrict__ a,
              const float* __restrict__ w_in, const float* __restrict__ b_in,
              const float* __restrict__ w_out, const float* __restrict__ b_out,
              const float* __restrict__ ln1_g, const float* __restrict__ ln1_b,
              const float* __restrict__ w1, const float* __restrict__ b1,
              const float* __restrict__ w2, const float* __restrict__ b2,
              const float* __restrict__ ln2_g, const float* __restrict__ ln2_b)
{
    extern __shared__ float sm[];
    float* xs   = sm;             // [32][128]    4096
    float* qkv  = sm + 4096;      // [32][385]   12320
    float* att  = sm + 16416;     // [4][32][32]  4096
    float* o_s  = sm + 20512;     // [32][128]    4096
    float* f_s  = sm;             // [32][1024]  32768 (overlays xs/qkv/att/o)
    float* h_s  = sm + 32768;     // [32][128]    4096
    float* h2   = sm + 36864;     // [32][128]    4096

    const int b = blockIdx.x >> 1;
    const int s = blockIdx.x & 1;
    const int tid = threadIdx.x;
    const int wid = tid >> 5, lane = tid & 31;
    const int e = g_sel_idx[b * 2 + s];
    const float gate = g_sel_gate[b * 2 + s];

    // load x = concat(z, a)
    for (int u = tid; u < NA * DD; u += 256) {
        int i = u >> 7, c = u & 127;
        xs[u] = (c < DZ) ? z[(b * NA + i) * DZ + c] : a[(b * NA + i) * DA + (c - DZ)];
    }
    __syncthreads();

    // qkv = x @ w_in[e]^T + b_in[e]
    gemm32<DD, 3 * DD, DD, QS, 0>(xs, w_in + (size_t)e * 3 * DD * DD,
                                  b_in + e * 3 * DD, qkv, nullptr, wid, lane);
    __syncthreads();

    // attention: warp -> (head h, qi-half)
    {
        const int h = wid & 3;
        const int qi0 = (wid >> 2) * 16;
        const float sc = 0.17677669529663687f; // 1/sqrt(32)
        const float* kb = qkv + lane * QS + DD + h * 32;
        for (int qi = qi0; qi < qi0 + 16; ++qi) {
            const float* qb = qkv + qi * QS + h * 32;
            float sv = 0.f;
            #pragma unroll
            for (int d = 0; d < 32; ++d) sv += qb[d] * kb[d];
            sv *= sc;
            float m = sv;
            #pragma unroll
            for (int off = 16; off; off >>= 1)
                m = fmaxf(m, __shfl_xor_sync(0xffffffffu, m, off));
            float ev = __expf(sv - m);
            float sum = ev;
            #pragma unroll
            for (int off = 16; off; off >>= 1)
                sum += __shfl_xor_sync(0xffffffffu, sum, off);
            att[h * 1024 + qi * 32 + lane] = ev / sum;
        }
        __syncwarp();
        for (int qi = qi0; qi < qi0 + 16; ++qi) {
            float accv = 0.f;
            const float* ar = att + h * 1024 + qi * 32;
            #pragma unroll
            for (int ki = 0; ki < 32; ++ki)
                accv += ar[ki] * qkv[ki * QS + 2 * DD + h * 32 + lane];
            o_s[qi * DD + h * 32 + lane] = accv;
        }
    }
    __syncthreads();

    // o @ w_out^T + b_out + x  -> h_s ; LN1
    gemm32<DD, DD, DD, DD, 2>(o_s, w_out + (size_t)e * DD * DD,
                              b_out + e * DD, h_s, xs, wid, lane);
    ln_rows(h_s, ln1_g + e * DD, ln1_b + e * DD, wid, lane);
    __syncthreads();

    // f = relu(h @ w1^T + b1)
    gemm32<DD, FF, DD, FF, 1>(h_s, w1 + (size_t)e * FF * DD,
                              b1 + e * FF, f_s, nullptr, wid, lane);
    __syncthreads();

    // h2 = f @ w2^T + b2 + h
    gemm32<FF, DD, FF, DD, 2>(f_s, w2 + (size_t)e * DD * FF,
                              b2 + e * DD, h2, h_s, wid, lane);

    // LN2 * gate -> slot buffer
    {
        __syncwarp();
        float* outp = g_slot + ((size_t)s * B_TOK + b) * (NA * DD);
        const float* g2 = ln2_g + e * DD;
        const float* be2 = ln2_b + e * DD;
        #pragma unroll
        for (int r = 0; r < 4; ++r) {
            int i = wid * 4 + r;
            float v[4], ssum = 0.f, ssq = 0.f;
            #pragma unroll
            for (int u = 0; u < 4; ++u) {
                v[u] = h2[i * DD + lane + 32 * u];
                ssum += v[u]; ssq += v[u] * v[u];
            }
            #pragma unroll
            for (int off = 16; off; off >>= 1) {
                ssum += __shfl_xor_sync(0xffffffffu, ssum, off);
                ssq  += __shfl_xor_sync(0xffffffffu, ssq,  off);
            }
            float mu = ssum * (1.0f / DD);
            float var = ssq * (1.0f / DD) - mu * mu;
            float rstd = rsqrtf(var + 1e-5f);
            #pragma unroll
            for (int u = 0; u < 4; ++u) {
                int c = lane + 32 * u;
                outp[i * DD + c] = gate * ((v[u] - mu) * rstd * g2[c] + be2[c]);
            }
        }
    }
}

// ---------------- head GEMM1: t = relu(Y @ head_w1^T + head_b1) ----------------
__global__ void __launch_bounds__(256)
head1_kernel(const float* __restrict__ hw1, const float* __restrict__ hb1)
{
    __shared__ float ys[32 * 128];
    const int tid = threadIdx.x;
    const int wid = tid >> 5, lane = tid & 31;
    const int tok0 = blockIdx.x * 32;
    const int jbase = blockIdx.y * 128;
    const int row0 = wid * 4;
    float acc[2][4][2] = {};

    for (int kc = 0; kc < NA * DD; kc += 128) {
        for (int u = tid; u < 32 * 128; u += 256) {
            int i = u >> 7, kk = u & 127;
            size_t gi = (size_t)(tok0 + i) * (NA * DD) + kc + kk;
            ys[u] = g_slot[gi] + g_slot[(size_t)B_TOK * NA * DD + gi];
        }
        __syncthreads();
        #pragma unroll
        for (int it = 0; it < 2; ++it) {
            int j = jbase + it * 64 + lane * 2;
            const float* w0p = hw1 + (size_t)j * (NA * DD) + kc;
            const float* w1p = w0p + NA * DD;
            #pragma unroll 4
            for (int k = 0; k < 128; k += 4) {
                float4 w0 = *reinterpret_cast<const float4*>(w0p + k);
                float4 w1 = *reinterpret_cast<const float4*>(w1p + k);
                #pragma unroll
                for (int r = 0; r < 4; ++r) {
                    float4 xa = *reinterpret_cast<const float4*>(ys + (row0 + r) * 128 + k);
                    acc[it][r][0] += xa.x * w0.x + xa.y * w0.y + xa.z * w0.z + xa.w * w0.w;
                    acc[it][r][1] += xa.x * w1.x + xa.y * w1.y + xa.z * w1.z + xa.w * w1.w;
                }
            }
        }
        __syncthreads();
    }
    #pragma unroll
    for (int it = 0; it < 2; ++it) {
        #pragma unroll
        for (int r = 0; r < 4; ++r) {
            #pragma unroll
            for (int c = 0; c < 2; ++c) {
                int j = jbase + it * 64 + lane * 2 + c;
                float v = fmaxf(acc[it][r][c] + hb1[j], 0.0f);
                g_t[(size_t)(tok0 + row0 + r) * HH + j] = v;
            }
        }
    }
}

// ---------------- head GEMM2: r = t @ head_w2^T + head_b2 ----------------
__global__ void head2_kernel(const float* __restrict__ hw2, const float* __restrict__ hb2,
                             float* __restrict__ out)
{
    const int b = blockIdx.x;
    const int wid = threadIdx.x >> 5, lane = threadIdx.x & 31;
    const float* trow = g_t + (size_t)b * HH;
    const float* w = hw2 + wid * HH;
    float acc = 0.f;
    for (int k = lane; k < HH; k += 32) acc += trow[k] * w[k];
    #pragma unroll
    for (int off = 16; off; off >>= 1) acc += __shfl_xor_sync(0xffffffffu, acc, off);
    if (lane == 0) out[b * NR + wid] = acc + hb2[wid];
}

// ---------------- load-balance loss (deterministic reduction) ----------------
__global__ void loss_kernel(const float* __restrict__ gates, float* __restrict__ out)
{
    __shared__ float s_imp[NE], s_load[NE], s_lse;
    const int tid = threadIdx.x;
    if (tid < NE) {
        float im = 0.f, ld = 0.f;
        for (int b = 0; b < B_TOK; ++b) {
            float g = gates[b * NE + tid];
            im += g;
            if (g > 0.f) ld += 1.f;
        }
        s_imp[tid] = im; s_load[tid] = ld;
    }
    if (tid == NE) {
        float sv = 0.f;
        for (int b = 0; b < B_TOK; ++b) sv += g_lse_tok[b];
        s_lse = sv;
    }
    __syncthreads();
    if (tid == 0) {
        float mi = 0.f, ml = 0.f;
        #pragma unroll
        for (int e = 0; e < NE; ++e) { mi += s_imp[e]; ml += s_load[e]; }
        mi *= (1.0f / NE); ml *= (1.0f / NE);
        float vi = 0.f, vl = 0.f;
        #pragma unroll
        for (int e = 0; e < NE; ++e) {
            float di = s_imp[e] - mi, dl = s_load[e] - ml;
            vi += di * di; vl += dl * dl;
        }
        vi *= (1.0f / (NE - 1)); vl *= (1.0f / (NE - 1));
        float loss = vi / (mi * mi + 1e-10f) + vl / (ml * ml + 1e-10f)
                   + s_lse * (1.0f / B_TOK);
        out[B_TOK * NR + B_TOK * NE] = loss;  // index 12288
    }
}

// ---------------- launch ----------------
extern "C" void kernel_launch(void* const* d_in, const int* in_sizes, int n_in,
                              void* d_out, int out_size)
{
    const float* z      = (const float*)d_in[0];
    const float* a      = (const float*)d_in[1];
    const float* w_gate = (const float*)d_in[2];
    const float* w_in   = (const float*)d_in[3];
    const float* b_in   = (const float*)d_in[4];
    const float* w_out  = (const float*)d_in[5];
    const float* b_out  = (const float*)d_in[6];
    const float* ln1_g  = (const float*)d_in[7];
    const float* ln1_b  = (const float*)d_in[8];
    const float* w1     = (const float*)d_in[9];
    const float* b1     = (const float*)d_in[10];
    const float* w2     = (const float*)d_in[11];
    const float* b2     = (const float*)d_in[12];
    const float* ln2_g  = (const float*)d_in[13];
    const float* ln2_b  = (const float*)d_in[14];
    const float* hw1    = (const float*)d_in[15];
    const float* hb1    = (const float*)d_in[16];
    const float* hw2    = (const float*)d_in[17];
    const float* hb2    = (const float*)d_in[18];
    float* out = (float*)d_out;
    float* gates_out = out + B_TOK * NR;   // r:[1024,4] then gates:[1024,8] then loss

    cudaFuncSetAttribute(expert_kernel, cudaFuncAttributeMaxDynamicSharedMemorySize, 163840);

    router_kernel<<<B_TOK, 128>>>(z, a, w_gate, gates_out);
    expert_kernel<<<2 * B_TOK, 256, 163840>>>(z, a, w_in, b_in, w_out, b_out,
                                              ln1_g, ln1_b, w1, b1, w2, b2, ln2_g, ln2_b);
    head1_kernel<<<dim3(B_TOK / 32, HH / 128), 256>>>(hw1, hb1);
    head2_kernel<<<B_TOK, 128>>>(hw2, hb2, out);
    loss_kernel<<<1, 32>>>(gates_out, out);
}

// round 2
// speedup vs baseline: 2.8011x; 2.8011x over previous
#include <cuda_runtime.h>
#include <math.h>
#include <stdint.h>

#define B_TOK 1024
#define NA    32
#define DZ    96
#define DA    32
#define DD    128
#define NE    8
#define FF    1024
#define HH    512
#define NR    4

// ---------------- device scratch (no allocations allowed) ----------------
__device__ float g_slot[2u * B_TOK * NA * DD];   // gate-scaled expert outputs (32 MB)
__device__ float g_t[B_TOK * HH];                // head hidden (2 MB)
__device__ int   g_sel_idx[B_TOK * 2];
__device__ float g_sel_gate[B_TOK * 2];
__device__ float g_lse_tok[B_TOK];

// transposed weights: Wt[k][j] row-major, per expert
__device__ float g_wint [NE * DD * 3 * DD];      // [e][128][384]
__device__ float g_woutt[NE * DD * DD];          // [e][128][128]
__device__ float g_w1t  [NE * DD * FF];          // [e][128][1024]
__device__ float g_w2t  [NE * FF * DD];          // [e][1024][128]
__device__ float g_hw1t [NA * DD * HH];          // [4096][512]

// ---------------- tiled transpose: src [R][C] -> dst [C][R], batched ----------------
__global__ void transpose_kernel(const float* __restrict__ src, int sel, int R, int C)
{
    float* dst = (sel == 0) ? g_wint : (sel == 1) ? g_woutt :
                 (sel == 2) ? g_w1t  : (sel == 3) ? g_w2t  : g_hw1t;
    __shared__ float tile[32][33];
    const size_t mb = (size_t)blockIdx.z * R * C;
    const float* s = src + mb;
    float* d = dst + mb;
    int c = blockIdx.x * 32 + threadIdx.x;
    int r0 = blockIdx.y * 32;
    #pragma unroll
    for (int i = threadIdx.y; i < 32; i += 8)
        tile[i][threadIdx.x] = s[(size_t)(r0 + i) * C + c];
    __syncthreads();
    int rr = r0 + threadIdx.x;
    int c0 = blockIdx.x * 32;
    #pragma unroll
    for (int i = threadIdx.y; i < 32; i += 8)
        d[(size_t)(c0 + i) * R + rr] = tile[threadIdx.x][i];
}

// ---------------- microkernel: acc[R][4] += As[row0..+R][0..K) @ Wt[0..K)[j0+lane*4 ..+3]
// As: smem, row stride sa (lane-uniform reads -> broadcast). Wt: gmem [K][ldw] transposed.
template<int K, int R>
__device__ __forceinline__ void mm_tile(const float* __restrict__ As, int row0, int sa,
                                        const float* __restrict__ Wt, int ldw, int j0,
                                        float acc[R][4], int lane)
{
    const float* wp = Wt + j0 + lane * 4;
    #pragma unroll 2
    for (int k = 0; k < K; k += 4) {
        float av[R][4];
        #pragma unroll
        for (int r = 0; r < R; ++r)
            *reinterpret_cast<float4*>(av[r]) =
                *reinterpret_cast<const float4*>(As + (row0 + r) * sa + k);
        #pragma unroll
        for (int kk = 0; kk < 4; ++kk) {
            float4 w = __ldg(reinterpret_cast<const float4*>(wp + (size_t)(k + kk) * ldw));
            #pragma unroll
            for (int r = 0; r < R; ++r) {
                float a = av[r][kk];
                acc[r][0] = fmaf(a, w.x, acc[r][0]);
                acc[r][1] = fmaf(a, w.y, acc[r][1]);
                acc[r][2] = fmaf(a, w.z, acc[r][2]);
                acc[r][3] = fmaf(a, w.w, acc[r][3]);
            }
        }
    }
}

// LayerNorm rows row0..row0+3, buffer stride 128
__device__ __forceinline__ void ln_rows4(float* __restrict__ buf, int row0,
                                         const float* __restrict__ g,
                                         const float* __restrict__ b, int lane)
{
    __syncwarp();
    #pragma unroll
    for (int r = 0; r < 4; ++r) {
        int i = row0 + r;
        float v[4], s = 0.f, ss = 0.f;
        #pragma unroll
        for (int u = 0; u < 4; ++u) {
            v[u] = buf[i * DD + lane + 32 * u];
            s += v[u]; ss += v[u] * v[u];
        }
        #pragma unroll
        for (int off = 16; off; off >>= 1) {
            s  += __shfl_xor_sync(0xffffffffu, s,  off);
            ss += __shfl_xor_sync(0xffffffffu, ss, off);
        }
        float mu = s * (1.0f / DD);
        float var = ss * (1.0f / DD) - mu * mu;
        float rstd = rsqrtf(var + 1e-5f);
        #pragma unroll
        for (int u = 0; u < 4; ++u) {
            int c = lane + 32 * u;
            buf[i * DD + c] = (v[u] - mu) * rstd * g[c] + b[c];
        }
    }
    __syncwarp();
}

// ---------------- router ----------------
__global__ void router_kernel(const float* __restrict__ z, const float* __restrict__ a,
                              const float* __restrict__ w_gate, float* __restrict__ gates_out)
{
    const int b = blockIdx.x;
    const int tid = threadIdx.x;
    float acc[NE] = {};
    for (int k = tid; k < NA * DD; k += 128) {
        int i = k >> 7, c = k & 127;
        float xv = (c < DZ) ? z[(b * NA + i) * DZ + c] : a[(b * NA + i) * DA + (c - DZ)];
        const float* wr = w_gate + (size_t)k * NE;
        #pragma unroll
        for (int e = 0; e < NE; ++e) acc[e] += xv * wr[e];
    }
    __shared__ float red[128 * NE];
    __shared__ float logits[NE];
    #pragma unroll
    for (int e = 0; e < NE; ++e) red[tid * NE + e] = acc[e];
    __syncthreads();
    if (tid < NE) {
        float s = 0.f;
        for (int t = 0; t < 128; ++t) s += red[t * NE + tid];
        logits[tid] = s;
    }
    __syncthreads();
    if (tid == 0) {
        int i0 = 0;
        #pragma unroll
        for (int e = 1; e < NE; ++e) if (logits[e] > logits[i0]) i0 = e;
        int i1 = (i0 == 0) ? 1 : 0;
        #pragma unroll
        for (int e = 0; e < NE; ++e) if (e != i0 && logits[e] > logits[i1]) i1 = e;
        float l0 = logits[i0], l1 = logits[i1];
        float m2 = fmaxf(l0, l1);
        float e0 = expf(l0 - m2), e1 = expf(l1 - m2);
        float inv = 1.0f / (e0 + e1);
        float g0 = e0 * inv, g1 = e1 * inv;
        #pragma unroll
        for (int e = 0; e < NE; ++e)
            gates_out[b * NE + e] = (e == i0) ? g0 : ((e == i1) ? g1 : 0.0f);
        g_sel_idx[b * 2 + 0] = i0;  g_sel_gate[b * 2 + 0] = g0;
        g_sel_idx[b * 2 + 1] = i1;  g_sel_gate[b * 2 + 1] = g1;
        float m = logits[0];
        #pragma unroll
        for (int e = 1; e < NE; ++e) m = fmaxf(m, logits[e]);
        float s = 0.f;
        #pragma unroll
        for (int e = 0; e < NE; ++e) s += expf(logits[e] - m);
        g_lse_tok[b] = m + logf(s);
    }
}

// ---------------- expert: one (token, slot) per block, 2 CTAs/SM ----------------
// smem (floats): xs 0..4096 | qs 4096 (stride 129, 4128) | ks 8224 | vs 12352 |
//                att 16480 (4096) | o 20576 (4096).  h overlays qs, f overlays ks.
#define SMEM_FLOATS 24672

__global__ void __launch_bounds__(256, 2)
expert_kernel(const float* __restrict__ z, const float* __restrict__ a,
              const float* __restrict__ b_in, const float* __restrict__ b_out,
              const float* __restrict__ ln1_g, const float* __restrict__ ln1_b,
              const float* __restrict__ b1, const float* __restrict__ b2,
              const float* __restrict__ ln2_g, const float* __restrict__ ln2_b)
{
    extern __shared__ float sm[];
    float* xs  = sm;
    float* qs  = sm + 4096;
    float* ks  = sm + 8224;
    float* vs  = sm + 12352;
    float* att = sm + 16480;
    float* o_s = sm + 20576;
    float* h_s = qs;   // overlay (qs dead after attention)
    float* f_s = ks;   // overlay (ks dead after attention)

    const int b = blockIdx.x >> 1;
    const int s = blockIdx.x & 1;
    const int tid = threadIdx.x;
    const int wid = tid >> 5, lane = tid & 31;
    const int row0 = wid * 4;
    const int e = g_sel_idx[b * 2 + s];
    const float gate = g_sel_gate[b * 2 + s];

    // x = concat(z, a)
    for (int u = tid; u < NA * DD; u += 256) {
        int i = u >> 7, c = u & 127;
        xs[u] = (c < DZ) ? z[(b * NA + i) * DZ + c] : a[(b * NA + i) * DA + (c - DZ)];
    }
    __syncthreads();

    // qkv = x @ w_in^T + b_in  (3 tiles of 128 -> q,k,v with row stride 129)
    {
        const float* wi = g_wint + (size_t)e * DD * 3 * DD;
        const float* bi = b_in + e * 3 * DD;
        #pragma unroll
        for (int t = 0; t < 3; ++t) {
            float acc[4][4] = {};
            mm_tile<DD, 4>(xs, row0, DD, wi, 3 * DD, t * 128, acc, lane);
            float* outb = (t == 0) ? qs : (t == 1) ? ks : vs;
            #pragma unroll
            for (int r = 0; r < 4; ++r)
                #pragma unroll
                for (int c = 0; c < 4; ++c) {
                    int j = lane * 4 + c;
                    outb[(row0 + r) * 129 + j] = acc[r][c] + bi[t * 128 + j];
                }
        }
    }
    __syncthreads();

    // attention: warp -> (head h, 16-q chunk)
    {
        const int h = wid & 3;
        const int qi0 = (wid >> 2) * 16;
        const float sc = 0.17677669529663687f;  // 1/sqrt(32)
        const float* kb = ks + lane * 129 + h * 32;
        for (int qi = qi0; qi < qi0 + 16; ++qi) {
            const float* qb = qs + qi * 129 + h * 32;
            float sv = 0.f;
            #pragma unroll
            for (int d = 0; d < 32; ++d) sv += qb[d] * kb[d];
            sv *= sc;
            float m = sv;
            #pragma unroll
            for (int off = 16; off; off >>= 1)
                m = fmaxf(m, __shfl_xor_sync(0xffffffffu, m, off));
            float ev = __expf(sv - m);
            float sum = ev;
            #pragma unroll
            for (int off = 16; off; off >>= 1)
                sum += __shfl_xor_sync(0xffffffffu, sum, off);
            att[h * 1024 + qi * 32 + lane] = ev / sum;
        }
        __syncwarp();
        for (int qi = qi0; qi < qi0 + 16; ++qi) {
            float accv = 0.f;
            const float* ar = att + h * 1024 + qi * 32;
            #pragma unroll
            for (int ki = 0; ki < 32; ++ki)
                accv += ar[ki] * vs[ki * 129 + h * 32 + lane];
            o_s[qi * DD + h * 32 + lane] = accv;
        }
    }
    __syncthreads();

    // h = LN1(o @ w_out^T + b_out + x)
    {
        float acc[4][4] = {};
        mm_tile<DD, 4>(o_s, row0, DD, g_woutt + (size_t)e * DD * DD, DD, 0, acc, lane);
        const float* bo = b_out + e * DD;
        #pragma unroll
        for (int r = 0; r < 4; ++r)
            #pragma unroll
            for (int c = 0; c < 4; ++c) {
                int j = lane * 4 + c;
                h_s[(row0 + r) * DD + j] = acc[r][c] + bo[j] + xs[(row0 + r) * DD + j];
            }
        ln_rows4(h_s, row0, ln1_g + e * DD, ln1_b + e * DD, lane);
    }

    // fused FFN: h2 accumulated in registers, f chunk-by-chunk (warp-local)
    float h2[4][4] = {};
    {
        const float* w1t = g_w1t + (size_t)e * DD * FF;
        const float* w2t = g_w2t + (size_t)e * FF * DD;
        const float* b1e = b1 + e * FF;
        #pragma unroll 1
        for (int c = 0; c < FF / 128; ++c) {
            float acc[4][4] = {};
            mm_tile<DD, 4>(h_s, row0, DD, w1t, FF, c * 128, acc, lane);
            #pragma unroll
            for (int r = 0; r < 4; ++r)
                #pragma unroll
                for (int cc = 0; cc < 4; ++cc) {
                    int j = lane * 4 + cc;
                    f_s[(row0 + r) * 128 + j] = fmaxf(acc[r][cc] + b1e[c * 128 + j], 0.0f);
                }
            __syncwarp();
            mm_tile<128, 4>(f_s, row0, 128, w2t + (size_t)c * 128 * DD, DD, 0, h2, lane);
            __syncwarp();
        }
    }

    // LN2(h2 + b2 + h) * gate -> slot buffer
    {
        float* outp = g_slot + ((size_t)s * B_TOK + b) * (NA * DD);
        const float* g2  = ln2_g + e * DD;
        const float* be2 = ln2_b + e * DD;
        const float* b2e = b2 + e * DD;
        #pragma unroll
        for (int r = 0; r < 4; ++r) {
            int i = row0 + r;
            float v[4], ssum = 0.f, ssq = 0.f;
            #pragma unroll
            for (int c = 0; c < 4; ++c) {
                int j = lane * 4 + c;
                v[c] = h2[r][c] + b2e[j] + h_s[i * DD + j];
                ssum += v[c]; ssq += v[c] * v[c];
            }
            #pragma unroll
            for (int off = 16; off; off >>= 1) {
                ssum += __shfl_xor_sync(0xffffffffu, ssum, off);
                ssq  += __shfl_xor_sync(0xffffffffu, ssq,  off);
            }
            float mu = ssum * (1.0f / DD);
            float var = ssq * (1.0f / DD) - mu * mu;
            float rstd = rsqrtf(var + 1e-5f);
            float4 ov;
            {
                int j = lane * 4;
                ov.x = gate * ((v[0] - mu) * rstd * g2[j + 0] + be2[j + 0]);
                ov.y = gate * ((v[1] - mu) * rstd * g2[j + 1] + be2[j + 1]);
                ov.z = gate * ((v[2] - mu) * rstd * g2[j + 2] + be2[j + 2]);
                ov.w = gate * ((v[3] - mu) * rstd * g2[j + 3] + be2[j + 3]);
            }
            *reinterpret_cast<float4*>(outp + i * DD + lane * 4) = ov;
        }
    }
}

// ---------------- head GEMM1: t = relu(Y @ head_w1^T + head_b1), transposed weights ----------------
__global__ void __launch_bounds__(256)
head1_kernel(const float* __restrict__ hb1)
{
    __shared__ float ys[16 * 128];
    const int tid = threadIdx.x;
    const int wid = tid >> 5, lane = tid & 31;
    const int tok0 = blockIdx.x * 16;
    const int j0 = blockIdx.y * 128;
    const int row0 = wid * 2;
    float acc[2][4] = {};

    #pragma unroll 1
    for (int c = 0; c < (NA * DD) / 128; ++c) {
        for (int u = tid; u < 16 * 128; u += 256) {
            int i = u >> 7, kk = u & 127;
            size_t gi = (size_t)(tok0 + i) * (NA * DD) + c * 128 + kk;
            ys[u] = g_slot[gi] + g_slot[(size_t)B_TOK * NA * DD + gi];
        }
        __syncthreads();
        mm_tile<128, 2>(ys, row0, 128, g_hw1t + (size_t)c * 128 * HH, HH, j0, acc, lane);
        __syncthreads();
    }
    #pragma unroll
    for (int r = 0; r < 2; ++r)
        #pragma unroll
        for (int cc = 0; cc < 4; ++cc) {
            int j = j0 + lane * 4 + cc;
            g_t[(size_t)(tok0 + row0 + r) * HH + j] = fmaxf(acc[r][cc] + hb1[j], 0.0f);
        }
}

// ---------------- head GEMM2 ----------------
__global__ void head2_kernel(const float* __restrict__ hw2, const float* __restrict__ hb2,
                             float* __restrict__ out)
{
    const int b = blockIdx.x;
    const int wid = threadIdx.x >> 5, lane = threadIdx.x & 31;
    const float* trow = g_t + (size_t)b * HH;
    const float* w = hw2 + wid * HH;
    float acc = 0.f;
    for (int k = lane; k < HH; k += 32) acc += trow[k] * w[k];
    #pragma unroll
    for (int off = 16; off; off >>= 1) acc += __shfl_xor_sync(0xffffffffu, acc, off);
    if (lane == 0) out[b * NR + wid] = acc + hb2[wid];
}

// ---------------- load-balance loss ----------------
__global__ void loss_kernel(const float* __restrict__ gates, float* __restrict__ out)
{
    __shared__ float s_imp[NE], s_load[NE], s_lse;
    const int tid = threadIdx.x;
    if (tid < NE) {
        float im = 0.f, ld = 0.f;
        for (int b = 0; b < B_TOK; ++b) {
            float g = gates[b * NE + tid];
            im += g;
            if (g > 0.f) ld += 1.f;
        }
        s_imp[tid] = im; s_load[tid] = ld;
    }
    if (tid == NE) {
        float sv = 0.f;
        for (int b = 0; b < B_TOK; ++b) sv += g_lse_tok[b];
        s_lse = sv;
    }
    __syncthreads();
    if (tid == 0) {
        float mi = 0.f, ml = 0.f;
        #pragma unroll
        for (int e = 0; e < NE; ++e) { mi += s_imp[e]; ml += s_load[e]; }
        mi *= (1.0f / NE); ml *= (1.0f / NE);
        float vi = 0.f, vl = 0.f;
        #pragma unroll
        for (int e = 0; e < NE; ++e) {
            float di = s_imp[e] - mi, dl = s_load[e] - ml;
            vi += di * di; vl += dl * dl;
        }
        vi *= (1.0f / (NE - 1)); vl *= (1.0f / (NE - 1));
        float loss = vi / (mi * mi + 1e-10f) + vl / (ml * ml + 1e-10f)
                   + s_lse * (1.0f / B_TOK);
        out[B_TOK * NR + B_TOK * NE] = loss;
    }
}

// ---------------- launch ----------------
extern "C" void kernel_launch(void* const* d_in, const int* in_sizes, int n_in,
                              void* d_out, int out_size)
{
    const float* z      = (const float*)d_in[0];
    const float* a      = (const float*)d_in[1];
    const float* w_gate = (const float*)d_in[2];
    const float* w_in   = (const float*)d_in[3];
    const float* b_in   = (const float*)d_in[4];
    const float* w_out  = (const float*)d_in[5];
    const float* b_out  = (const float*)d_in[6];
    const float* ln1_g  = (const float*)d_in[7];
    const float* ln1_b  = (const float*)d_in[8];
    const float* w1     = (const float*)d_in[9];
    const float* b1     = (const float*)d_in[10];
    const float* w2     = (const float*)d_in[11];
    const float* b2     = (const float*)d_in[12];
    const float* ln2_g  = (const float*)d_in[13];
    const float* ln2_b  = (const float*)d_in[14];
    const float* hw1    = (const float*)d_in[15];
    const float* hb1    = (const float*)d_in[16];
    const float* hw2    = (const float*)d_in[17];
    const float* hb2    = (const float*)d_in[18];
    float* out = (float*)d_out;
    float* gates_out = out + B_TOK * NR;

    static bool attr_set = false;
    if (!attr_set) {
        cudaFuncSetAttribute(expert_kernel, cudaFuncAttributeMaxDynamicSharedMemorySize,
                             SMEM_FLOATS * 4);
        attr_set = true;
    }

    dim3 tb(32, 8);
    transpose_kernel<<<dim3(4, 12, 8),  tb>>>(w_in,  0, 3 * DD, DD);
    transpose_kernel<<<dim3(4, 4, 8),   tb>>>(w_out, 1, DD, DD);
    transpose_kernel<<<dim3(4, 32, 8),  tb>>>(w1,    2, FF, DD);
    transpose_kernel<<<dim3(32, 4, 8),  tb>>>(w2,    3, DD, FF);
    transpose_kernel<<<dim3(128, 16, 1),tb>>>(hw1,   4, HH, NA * DD);

    router_kernel<<<B_TOK, 128>>>(z, a, w_gate, gates_out);
    expert_kernel<<<2 * B_TOK, 256, SMEM_FLOATS * 4>>>(z, a, b_in, b_out,
                                                       ln1_g, ln1_b, b1, b2, ln2_g, ln2_b);
    head1_kernel<<<dim3(B_TOK / 16, HH / 128), 256>>>(hb1);
    head2_kernel<<<B_TOK, 128>>>(hw2, hb2, out);
    loss_kernel<<<1, 32>>>(gates_out, out);
}